// round 7
// baseline (speedup 1.0000x reference)
#include <cuda_runtime.h>
#include <math.h>

#define HW 4096
#define NB 2

// Scratch (module-load allocated, not runtime alloc)
__device__ float g_M [(size_t)NB * HW * HW];   // M[b][j][i]
__device__ float g_MT[(size_t)NB * HW * HW];   // M[b][i][j] (transpose)
__device__ float g_inv[4][NB * HW];            // 0:src3 1:tgt3 2:src4 3:tgt4

// ---------------------------------------------------------------------------
// Kernel 1: per-position inverse channel norms.  grid (32, 4) x 256
// ---------------------------------------------------------------------------
__global__ void norm_kernel(const float* __restrict__ s3, const float* __restrict__ t3,
                            const float* __restrict__ s4, const float* __restrict__ t4)
{
    int gid   = blockIdx.x * 256 + threadIdx.x;   // 0..8191 = b*4096 + pos
    int which = blockIdx.y;
    const float* x; int C;
    if      (which == 0) { x = s3; C = 1024; }
    else if (which == 1) { x = t3; C = 1024; }
    else if (which == 2) { x = s4; C = 2048; }
    else                 { x = t4; C = 2048; }

    int b = gid >> 12, pos = gid & (HW - 1);
    const float* p = x + (size_t)b * C * HW + pos;
    float ss0 = 0.f, ss1 = 0.f, ss2 = 0.f, ss3 = 0.f;
    for (int c = 0; c < C; c += 4) {
        float a0 = p[(size_t)(c + 0) * HW];
        float a1 = p[(size_t)(c + 1) * HW];
        float a2 = p[(size_t)(c + 2) * HW];
        float a3 = p[(size_t)(c + 3) * HW];
        ss0 = fmaf(a0, a0, ss0); ss1 = fmaf(a1, a1, ss1);
        ss2 = fmaf(a2, a2, ss2); ss3 = fmaf(a3, a3, ss3);
    }
    g_inv[which][gid] = rsqrtf((ss0 + ss1) + (ss2 + ss3) + 1e-6f);
}

// ---------------------------------------------------------------------------
// Kernel 2: tiled fp32 GEMM, C[j,i] = sum_c T[c,j]*S[c,i], epilogue fused.
//   MODE 0: M = relu(C3 * invT3[j] * invS3[i])
//   MODE 1: m = M * relu(C4 * invT4[j] * invS4[i]); M = m; MT = m
// 128x128 tile, BK=16, 256 threads, 8x8 per thread.
// ---------------------------------------------------------------------------
template<int MODE>
__global__ void __launch_bounds__(256, 2)
gemm_kernel(const float* __restrict__ Tg, const float* __restrict__ Sg, int C)
{
    __shared__ float Ts[16][128];
    __shared__ float Ss[16][128];

    const int b  = blockIdx.z;
    const int j0 = blockIdx.y * 128;
    const int i0 = blockIdx.x * 128;
    const float* Tb = Tg + (size_t)b * C * HW;
    const float* Sb = Sg + (size_t)b * C * HW;

    const int tid = threadIdx.x;
    const int tx  = tid & 15;    // i sub-tile
    const int ty  = tid >> 4;    // j sub-tile

    float acc[8][8];
#pragma unroll
    for (int u = 0; u < 8; ++u)
#pragma unroll
        for (int v = 0; v < 8; ++v) acc[u][v] = 0.f;

    for (int k0 = 0; k0 < C; k0 += 16) {
#pragma unroll
        for (int l = 0; l < 8; ++l) {
            int idx = tid + l * 256;
            int r = idx >> 7, col = idx & 127;
            Ts[r][col] = Tb[(size_t)(k0 + r) * HW + j0 + col];
            Ss[r][col] = Sb[(size_t)(k0 + r) * HW + i0 + col];
        }
        __syncthreads();
#pragma unroll
        for (int k = 0; k < 16; ++k) {
            float a[8], bv[8];
#pragma unroll
            for (int u = 0; u < 8; ++u) a[u]  = Ts[k][ty * 8 + u];
#pragma unroll
            for (int v = 0; v < 8; ++v) bv[v] = Ss[k][tx * 8 + v];
#pragma unroll
            for (int u = 0; u < 8; ++u)
#pragma unroll
                for (int v = 0; v < 8; ++v)
                    acc[u][v] = fmaf(a[u], bv[v], acc[u][v]);
        }
        __syncthreads();
    }

    const float* invT = g_inv[MODE == 0 ? 1 : 3] + b * HW;
    const float* invS = g_inv[MODE == 0 ? 0 : 2] + b * HW;
    float itv[8], isv[8];
#pragma unroll
    for (int u = 0; u < 8; ++u) itv[u] = invT[j0 + ty * 8 + u];
#pragma unroll
    for (int v = 0; v < 8; ++v) isv[v] = invS[i0 + tx * 8 + v];

#pragma unroll
    for (int u = 0; u < 8; ++u) {
        int j = j0 + ty * 8 + u;
        size_t rowo = ((size_t)b * HW + j) * HW;
#pragma unroll
        for (int v = 0; v < 8; ++v) {
            int i = i0 + tx * 8 + v;
            float c = acc[u][v] * itv[u] * isv[v];
            c = fmaxf(c, 0.f);
            if (MODE == 0) {
                g_M[rowo + i] = c;
            } else {
                float m = g_M[rowo + i] * c;
                g_M[rowo + i] = m;
                g_MT[((size_t)b * HW + i) * HW + j] = m;
            }
        }
    }
}

// ---------------------------------------------------------------------------
// Kernel 3: soft-argmax per column.  grid (4096, 2 batches, 2 dirs) x 256.
//   dir 0 (s2t): rows of MT   -> out offset 0
//   dir 1 (t2s): rows of M    -> out offset 32768
// ---------------------------------------------------------------------------
__global__ void __launch_bounds__(256)
softargmax_kernel(float* __restrict__ out)
{
    __shared__ float gtab[64];
    __shared__ float redf[8];
    __shared__ int   redi[8];
    __shared__ float bc[2];
    __shared__ float r3[3][8];

    const int pos = blockIdx.x;
    const int b   = blockIdx.y;
    const int dir = blockIdx.z;
    const int tid = threadIdx.x;
    const int lane = tid & 31, wid = tid >> 5;

    const float* row = (dir == 0 ? g_MT : g_M) + ((size_t)b * HW + pos) * HW;

    if (tid < 64) gtab[tid] = expf(-(float)(tid * tid) * (1.0f / 50.0f));

    // ---- pass 1: load to registers + sum of squares
    float xr[16];
    float ss = 0.f;
#pragma unroll
    for (int s = 0; s < 16; ++s) {
        float x = row[tid + s * 256];
        xr[s] = x;
        ss = fmaf(x, x, ss);
    }
    for (int o = 16; o; o >>= 1) ss += __shfl_down_sync(0xffffffffu, ss, o);
    if (lane == 0) redf[wid] = ss;
    __syncthreads();
    if (wid == 0) {
        float v = (lane < 8) ? redf[lane] : 0.f;
        for (int o = 4; o; o >>= 1) v += __shfl_down_sync(0xffffffffu, v, o);
        if (lane == 0) bc[0] = rsqrtf(v + 1e-6f);
    }
    __syncthreads();
    const float invn = bc[0];

    // ---- pass 2: argmax (first occurrence on ties)
    float bvv = -1.f; int bj = HW;
#pragma unroll
    for (int s = 0; s < 16; ++s) {
        float x = xr[s];
        int j = tid + s * 256;
        if (x > bvv) { bvv = x; bj = j; }   // j ascending within thread
    }
    for (int o = 16; o; o >>= 1) {
        float ov = __shfl_down_sync(0xffffffffu, bvv, o);
        int   oj = __shfl_down_sync(0xffffffffu, bj,  o);
        if (ov > bvv || (ov == bvv && oj < bj)) { bvv = ov; bj = oj; }
    }
    __syncthreads();                 // redf reuse safety
    if (lane == 0) { redf[wid] = bvv; redi[wid] = bj; }
    __syncthreads();
    if (tid == 0) {
        float bestv = redf[0]; int bestj = redi[0];
        for (int q = 1; q < 8; ++q)
            if (redf[q] > bestv || (redf[q] == bestv && redi[q] < bestj)) {
                bestv = redf[q]; bestj = redi[q];
            }
        redi[0] = bestj;
    }
    __syncthreads();
    const int amax = redi[0];
    const int ax = amax & 63, ay = amax >> 6;

    // ---- pass 3: c = gauss * normalized value; track max.
    // gauss < 1e-6 => mark with sentinel -1 (treated as e = e0 in pass 4;
    // error bound ~3e-5 on output coords).
    float cm = -1.f;
#pragma unroll
    for (int s = 0; s < 16; ++s) {
        int j = tid + s * 256;
        int dx = (j & 63) - ax; dx = dx < 0 ? -dx : dx;
        int dy = (j >> 6) - ay; dy = dy < 0 ? -dy : dy;
        float g = gtab[dx] * gtab[dy];
        float c = (g < 1e-6f) ? -1.f : g * xr[s] * invn;
        xr[s] = c;
        cm = fmaxf(cm, c);
    }
    for (int o = 16; o; o >>= 1) cm = fmaxf(cm, __shfl_down_sync(0xffffffffu, cm, o));
    __syncthreads();
    if (lane == 0) redf[wid] = cm;
    __syncthreads();
    if (wid == 0) {
        float v = (lane < 8) ? redf[lane] : -1.f;
        for (int o = 4; o; o >>= 1) v = fmaxf(v, __shfl_down_sync(0xffffffffu, v, o));
        if (lane == 0) bc[1] = v;
    }
    __syncthreads();
    const float m  = bc[1];
    const float e0 = __expf(-50.f * m);

    // ---- pass 4: stable softmax + soft-argmax sums.
    // Skipped (sentinel) elements contribute e0 each: sum(xn)=sum(yn)=0 over
    // the full grid, so they only add 4096*e0 to the denominator.
    float se = 0.f, sx = 0.f, sy = 0.f;
#pragma unroll
    for (int s = 0; s < 16; ++s) {
        float c = xr[s];
        if (c >= 0.f) {
            int j = tid + s * 256;
            float e = __expf(50.f * (c - m)) - e0;
            float xn = fmaf((float)(j & 63), 2.f / 63.f, -1.f);
            float yn = fmaf((float)(j >> 6), 2.f / 63.f, -1.f);
            se += e;
            sx = fmaf(e, xn, sx);
            sy = fmaf(e, yn, sy);
        }
    }
    for (int o = 16; o; o >>= 1) {
        se += __shfl_down_sync(0xffffffffu, se, o);
        sx += __shfl_down_sync(0xffffffffu, sx, o);
        sy += __shfl_down_sync(0xffffffffu, sy, o);
    }
    if (lane == 0) { r3[0][wid] = se; r3[1][wid] = sx; r3[2][wid] = sy; }
    __syncthreads();
    if (tid == 0) {
        float tse = 0.f, tsx = 0.f, tsy = 0.f;
        for (int q = 0; q < 8; ++q) { tse += r3[0][q]; tsx += r3[1][q]; tsy += r3[2][q]; }
        float denom = tse + 4096.f * e0;
        float gx = tsx / denom;
        float gy = tsy / denom;
        // grid layout (b, h, w, 2); s2t at offset 0, t2s at 32768
        size_t ob = (size_t)dir * 32768 + (((size_t)b * 64 + (pos >> 6)) * 64 + (pos & 63)) * 2;
        out[ob]     = gx;
        out[ob + 1] = gy;
    }
}

// ---------------------------------------------------------------------------
// Kernel 4: flow outputs are exactly zero (grid_x - grid_x).
// ---------------------------------------------------------------------------
__global__ void zero_kernel(float* __restrict__ out)
{
    int i = blockIdx.x * blockDim.x + threadIdx.x;   // 0..32767
    int base = (i < 16384) ? 16384 : 49152;
    out[base + (i & 16383)] = 0.f;
}

// ---------------------------------------------------------------------------
extern "C" void kernel_launch(void* const* d_in, const int* in_sizes, int n_in,
                              void* d_out, int out_size)
{
    const float* s3 = (const float*)d_in[0];
    const float* t3 = (const float*)d_in[1];
    const float* s4 = (const float*)d_in[2];
    const float* t4 = (const float*)d_in[3];
    float* out = (float*)d_out;

    norm_kernel<<<dim3(32, 4), 256>>>(s3, t3, s4, t4);
    gemm_kernel<0><<<dim3(32, 32, NB), 256>>>(t3, s3, 1024);
    gemm_kernel<1><<<dim3(32, 32, NB), 256>>>(t4, s4, 2048);
    softargmax_kernel<<<dim3(HW, NB, 2), 256>>>(out);
    zero_kernel<<<64, 512>>>(out);
}

// round 9
// speedup vs baseline: 2.4128x; 2.4128x over previous
#include <cuda_runtime.h>
#include <cuda_fp16.h>
#include <stdint.h>
#include <math.h>

#define HW 4096
#define NB 2

__device__ float g_M [(size_t)NB * HW * HW];   // M[b][j][i]
__device__ float g_MT[(size_t)NB * HW * HW];   // M[b][i][j]
__device__ float g_inv[4][NB * HW];            // 0:src3 1:tgt3 2:src4 3:tgt4

// ---------------------------------------------------------------------------
// helpers
// ---------------------------------------------------------------------------
__device__ __forceinline__ uint32_t su32(const void* p) {
    uint32_t a;
    asm("{ .reg .u64 t; cvta.to.shared.u64 t, %1; cvt.u32.u64 %0, t; }" : "=r"(a) : "l"(p));
    return a;
}
__device__ __forceinline__ void ldmx4(uint32_t* r, uint32_t a) {
    asm volatile("ldmatrix.sync.aligned.m8n8.x4.shared.b16 {%0,%1,%2,%3}, [%4];"
                 : "=r"(r[0]), "=r"(r[1]), "=r"(r[2]), "=r"(r[3]) : "r"(a));
}
__device__ __forceinline__ void ldmx2(uint32_t* r, uint32_t a) {
    asm volatile("ldmatrix.sync.aligned.m8n8.x2.shared.b16 {%0,%1}, [%2];"
                 : "=r"(r[0]), "=r"(r[1]) : "r"(a));
}
__device__ __forceinline__ void mma16816(float* d, const uint32_t* a, const uint32_t* b) {
    asm volatile(
        "mma.sync.aligned.m16n8k16.row.col.f32.f16.f16.f32 "
        "{%0,%1,%2,%3}, {%4,%5,%6,%7}, {%8,%9}, {%0,%1,%2,%3};"
        : "+f"(d[0]), "+f"(d[1]), "+f"(d[2]), "+f"(d[3])
        : "r"(a[0]), "r"(a[1]), "r"(a[2]), "r"(a[3]), "r"(b[0]), "r"(b[1]));
}

// ---------------------------------------------------------------------------
// Kernel 1: per-position inverse channel norms.
// ---------------------------------------------------------------------------
__global__ void norm_kernel(const float* __restrict__ s3, const float* __restrict__ t3,
                            const float* __restrict__ s4, const float* __restrict__ t4)
{
    int gid   = blockIdx.x * 256 + threadIdx.x;
    int which = blockIdx.y;
    const float* x; int C;
    if      (which == 0) { x = s3; C = 1024; }
    else if (which == 1) { x = t3; C = 1024; }
    else if (which == 2) { x = s4; C = 2048; }
    else                 { x = t4; C = 2048; }

    int b = gid >> 12, pos = gid & (HW - 1);
    const float* p = x + (size_t)b * C * HW + pos;
    float ss0 = 0.f, ss1 = 0.f, ss2 = 0.f, ss3 = 0.f;
    for (int c = 0; c < C; c += 4) {
        float a0 = p[(size_t)(c + 0) * HW];
        float a1 = p[(size_t)(c + 1) * HW];
        float a2 = p[(size_t)(c + 2) * HW];
        float a3 = p[(size_t)(c + 3) * HW];
        ss0 = fmaf(a0, a0, ss0); ss1 = fmaf(a1, a1, ss1);
        ss2 = fmaf(a2, a2, ss2); ss3 = fmaf(a3, a3, ss3);
    }
    g_inv[which][gid] = rsqrtf((ss0 + ss1) + (ss2 + ss3) + 1e-6f);
}

// ---------------------------------------------------------------------------
// GEMM chunk loaders.  Chunk = 32 channels of A (128 pos) + B (128 pos),
// split into fp16 hi/lo, stored K-contiguous [x][c] with XOR-swizzled 16B
// chunks:  byte = x*64 + ((c/8 ^ ((x>>1)&3)) << 4)   (+2B within chunk).
// Stage layout (32KB): Ah 0 | Al 8K | Bh 16K | Bl 24K.
// ---------------------------------------------------------------------------
__device__ __forceinline__ void ldg_chunk(const float* __restrict__ A,
                                          const float* __restrict__ B,
                                          int j0, int i0, int t, float* v, int tid)
{
#pragma unroll
    for (int it = 0; it < 4; ++it) {
        int id = it * 256 + tid;
        int x = id & 127, q = (id >> 7) & 3;
        const float* g = ((it < 2) ? A + j0 : B + i0) + (size_t)(t * 32 + q * 8) * HW + x;
#pragma unroll
        for (int r = 0; r < 8; ++r) v[it * 8 + r] = __ldg(g + (size_t)r * HW);
    }
}

__device__ __forceinline__ void sts_chunk(const float* v, char* st, int tid)
{
#pragma unroll
    for (int it = 0; it < 4; ++it) {
        int id = it * 256 + tid;
        int x = id & 127, q = (id >> 7) & 3;
        union { __half2 h2[4]; uint4 u; } H, L;
#pragma unroll
        for (int p = 0; p < 4; ++p) {
            float a = v[it * 8 + 2 * p], bb = v[it * 8 + 2 * p + 1];
            __half ha = __float2half_rn(a), hb = __float2half_rn(bb);
            H.h2[p] = __halves2half2(ha, hb);
            L.h2[p] = __halves2half2(__float2half_rn(a  - __half2float(ha)),
                                     __float2half_rn(bb - __half2float(hb)));
        }
        uint32_t off = (uint32_t)(x * 64 + ((q ^ ((x >> 1) & 3)) << 4));
        char* base = st + ((it >= 2) ? 16384 : 0);
        *reinterpret_cast<uint4*>(base + off)        = H.u;
        *reinterpret_cast<uint4*>(base + 8192 + off) = L.u;
    }
}

// ---------------------------------------------------------------------------
// Kernel 2: mma.sync fp16-split GEMM, CTA tile 128(j) x 128(i), BK=32,
// 8 warps of 64x32, double-buffered (2 x 32KB dyn smem).
//   MODE 0: g_M = relu(D * invT3[j] * invS3[i])
//   MODE 1: m = g_M * relu(D * invT4[j] * invS4[i]); g_M = m; g_MT^T = m
// ---------------------------------------------------------------------------
#define SMEM_DYN 65536

template<int MODE>
__global__ void __launch_bounds__(256)
gemm_mma_kernel(const float* __restrict__ Tg, const float* __restrict__ Sg)
{
    constexpr int C   = MODE ? 2048 : 1024;
    constexpr int NCH = C / 32;
    constexpr int TI  = MODE ? 3 : 1;
    constexpr int SI  = MODE ? 2 : 0;

    extern __shared__ char sm[];
    const int tid  = threadIdx.x;
    const int lane = tid & 31;
    const int wid  = tid >> 5;
    const int wj   = wid >> 2;           // 0..1 (64 rows each)
    const int wi   = wid & 3;            // 0..3 (32 cols each)
    const int b  = blockIdx.z;
    const int i0 = blockIdx.x * 128;
    const int j0 = blockIdx.y * 128;

    const float* Tb = Tg + (size_t)b * C * HW;
    const float* Sb = Sg + (size_t)b * C * HW;
    const uint32_t sb0 = su32(sm);

    // per-thread ldmatrix address components
    uint32_t aoff[4], aSw[4];
#pragma unroll
    for (int mi = 0; mi < 4; ++mi) {
        int x = wj * 64 + mi * 16 + (lane & 15);
        aoff[mi] = (uint32_t)(x * 64);
        aSw[mi]  = (uint32_t)((x >> 1) & 3);
    }
    const uint32_t hi16 = (uint32_t)((lane >> 4) & 1);
    const int ln = lane & 15;
    uint32_t boff[4], bSw[4];
#pragma unroll
    for (int ni = 0; ni < 4; ++ni) {
        int x = wi * 32 + ni * 8 + (ln & 7);
        boff[ni] = (uint32_t)(x * 64);
        bSw[ni]  = (uint32_t)((x >> 1) & 3);
    }
    const uint32_t bHalf = (uint32_t)((ln >> 3) & 1);

    float acc[4][4][4];
#pragma unroll
    for (int mi = 0; mi < 4; ++mi)
#pragma unroll
        for (int ni = 0; ni < 4; ++ni)
#pragma unroll
            for (int e = 0; e < 4; ++e) acc[mi][ni][e] = 0.f;

    float vst[32];
    ldg_chunk(Tb, Sb, j0, i0, 0, vst, tid);
    sts_chunk(vst, sm, tid);
    __syncthreads();

    for (int t = 0; t < NCH; ++t) {
        if (t + 1 < NCH) ldg_chunk(Tb, Sb, j0, i0, t + 1, vst, tid);

        const uint32_t sb = sb0 + (uint32_t)((t & 1) * 32768);
#pragma unroll
        for (int ks = 0; ks < 2; ++ks) {
            uint32_t ah[4][4], al[4][4];
#pragma unroll
            for (int mi = 0; mi < 4; ++mi) {
                uint32_t adr = sb + aoff[mi] + ((((uint32_t)(2 * ks) + hi16) ^ aSw[mi]) << 4);
                ldmx4(ah[mi], adr);
                ldmx4(al[mi], adr + 8192);
            }
#pragma unroll
            for (int ni = 0; ni < 4; ++ni) {
                uint32_t badr = sb + 16384 + boff[ni] +
                                ((((uint32_t)(2 * ks) + bHalf) ^ bSw[ni]) << 4);
                uint32_t bh[2], bl[2];
                ldmx2(bh, badr);
                ldmx2(bl, badr + 8192);
#pragma unroll
                for (int mi = 0; mi < 4; ++mi) {
                    mma16816(acc[mi][ni], ah[mi], bh);
                    mma16816(acc[mi][ni], ah[mi], bl);
                    mma16816(acc[mi][ni], al[mi], bh);
                }
            }
        }
        if (t + 1 < NCH) sts_chunk(vst, sm + ((t + 1) & 1) * 32768, tid);
        __syncthreads();
    }

    // ---- epilogue: write directly from fragments (32B-sector friendly) ----
    const float* invT = g_inv[TI] + (size_t)b * HW;
    const float* invS = g_inv[SI] + (size_t)b * HW;
    const int gid = lane >> 2, tig = lane & 3;
    const int jb = j0 + wj * 64 + gid;
    const int ib = i0 + wi * 32 + tig * 2;

    float tS[4][2];
#pragma unroll
    for (int mi = 0; mi < 4; ++mi) {
        tS[mi][0] = __ldg(invT + jb + mi * 16);
        tS[mi][1] = __ldg(invT + jb + mi * 16 + 8);
    }
    float2 sS[4];
#pragma unroll
    for (int ni = 0; ni < 4; ++ni)
        sS[ni] = *reinterpret_cast<const float2*>(invS + ib + ni * 8);

#pragma unroll
    for (int mi = 0; mi < 4; ++mi) {
        const int j = jb + mi * 16;
        const size_t row0 = ((size_t)b * HW + j) * HW;
        const size_t row8 = row0 + (size_t)8 * HW;
#pragma unroll
        for (int ni = 0; ni < 4; ++ni) {
            const int i = ib + ni * 8;
            float c0 = fmaxf(acc[mi][ni][0] * tS[mi][0] * sS[ni].x, 0.f);
            float c1 = fmaxf(acc[mi][ni][1] * tS[mi][0] * sS[ni].y, 0.f);
            float c2 = fmaxf(acc[mi][ni][2] * tS[mi][1] * sS[ni].x, 0.f);
            float c3 = fmaxf(acc[mi][ni][3] * tS[mi][1] * sS[ni].y, 0.f);
            if (MODE == 0) {
                *reinterpret_cast<float2*>(&g_M[row0 + i]) = make_float2(c0, c1);
                *reinterpret_cast<float2*>(&g_M[row8 + i]) = make_float2(c2, c3);
            } else {
                float2 o0 = *reinterpret_cast<const float2*>(&g_M[row0 + i]);
                float2 o8 = *reinterpret_cast<const float2*>(&g_M[row8 + i]);
                float m0 = o0.x * c0, m1 = o0.y * c1;
                float m2 = o8.x * c2, m3 = o8.y * c3;
                *reinterpret_cast<float2*>(&g_M[row0 + i]) = make_float2(m0, m1);
                *reinterpret_cast<float2*>(&g_M[row8 + i]) = make_float2(m2, m3);
                const size_t tc0 = ((size_t)b * HW + i) * HW;
                g_MT[tc0 + j]          = m0;
                g_MT[tc0 + HW + j]     = m1;
                g_MT[tc0 + j + 8]      = m2;
                g_MT[tc0 + HW + j + 8] = m3;
            }
        }
    }
}

// ---------------------------------------------------------------------------
// Kernel 3: soft-argmax per column (unchanged from passing version).
// ---------------------------------------------------------------------------
__global__ void __launch_bounds__(256)
softargmax_kernel(float* __restrict__ out)
{
    __shared__ float gtab[64];
    __shared__ float redf[8];
    __shared__ int   redi[8];
    __shared__ float bc[2];
    __shared__ float r3[3][8];

    const int pos = blockIdx.x;
    const int b   = blockIdx.y;
    const int dir = blockIdx.z;
    const int tid = threadIdx.x;
    const int lane = tid & 31, wid = tid >> 5;

    const float* row = (dir == 0 ? g_MT : g_M) + ((size_t)b * HW + pos) * HW;

    if (tid < 64) gtab[tid] = expf(-(float)(tid * tid) * (1.0f / 50.0f));

    float xr[16];
    float ss = 0.f;
#pragma unroll
    for (int s = 0; s < 16; ++s) {
        float x = row[tid + s * 256];
        xr[s] = x;
        ss = fmaf(x, x, ss);
    }
    for (int o = 16; o; o >>= 1) ss += __shfl_down_sync(0xffffffffu, ss, o);
    if (lane == 0) redf[wid] = ss;
    __syncthreads();
    if (wid == 0) {
        float v = (lane < 8) ? redf[lane] : 0.f;
        for (int o = 4; o; o >>= 1) v += __shfl_down_sync(0xffffffffu, v, o);
        if (lane == 0) bc[0] = rsqrtf(v + 1e-6f);
    }
    __syncthreads();
    const float invn = bc[0];

    float bvv = -1.f; int bj = HW;
#pragma unroll
    for (int s = 0; s < 16; ++s) {
        float x = xr[s];
        int j = tid + s * 256;
        if (x > bvv) { bvv = x; bj = j; }
    }
    for (int o = 16; o; o >>= 1) {
        float ov = __shfl_down_sync(0xffffffffu, bvv, o);
        int   oj = __shfl_down_sync(0xffffffffu, bj,  o);
        if (ov > bvv || (ov == bvv && oj < bj)) { bvv = ov; bj = oj; }
    }
    __syncthreads();
    if (lane == 0) { redf[wid] = bvv; redi[wid] = bj; }
    __syncthreads();
    if (tid == 0) {
        float bestv = redf[0]; int bestj = redi[0];
        for (int q = 1; q < 8; ++q)
            if (redf[q] > bestv || (redf[q] == bestv && redi[q] < bestj)) {
                bestv = redf[q]; bestj = redi[q];
            }
        redi[0] = bestj;
    }
    __syncthreads();
    const int amax = redi[0];
    const int ax = amax & 63, ay = amax >> 6;

    float cm = -1.f;
#pragma unroll
    for (int s = 0; s < 16; ++s) {
        int j = tid + s * 256;
        int dx = (j & 63) - ax; dx = dx < 0 ? -dx : dx;
        int dy = (j >> 6) - ay; dy = dy < 0 ? -dy : dy;
        float g = gtab[dx] * gtab[dy];
        float c = (g < 1e-6f) ? -1.f : g * xr[s] * invn;
        xr[s] = c;
        cm = fmaxf(cm, c);
    }
    for (int o = 16; o; o >>= 1) cm = fmaxf(cm, __shfl_down_sync(0xffffffffu, cm, o));
    __syncthreads();
    if (lane == 0) redf[wid] = cm;
    __syncthreads();
    if (wid == 0) {
        float v = (lane < 8) ? redf[lane] : -1.f;
        for (int o = 4; o; o >>= 1) v = fmaxf(v, __shfl_down_sync(0xffffffffu, v, o));
        if (lane == 0) bc[1] = v;
    }
    __syncthreads();
    const float m  = bc[1];
    const float e0 = __expf(-50.f * m);

    float se = 0.f, sx = 0.f, sy = 0.f;
#pragma unroll
    for (int s = 0; s < 16; ++s) {
        float c = xr[s];
        if (c >= 0.f) {
            int j = tid + s * 256;
            float e = __expf(50.f * (c - m)) - e0;
            float xn = fmaf((float)(j & 63), 2.f / 63.f, -1.f);
            float yn = fmaf((float)(j >> 6), 2.f / 63.f, -1.f);
            se += e;
            sx = fmaf(e, xn, sx);
            sy = fmaf(e, yn, sy);
        }
    }
    for (int o = 16; o; o >>= 1) {
        se += __shfl_down_sync(0xffffffffu, se, o);
        sx += __shfl_down_sync(0xffffffffu, sx, o);
        sy += __shfl_down_sync(0xffffffffu, sy, o);
    }
    if (lane == 0) { r3[0][wid] = se; r3[1][wid] = sx; r3[2][wid] = sy; }
    __syncthreads();
    if (tid == 0) {
        float tse = 0.f, tsx = 0.f, tsy = 0.f;
        for (int q = 0; q < 8; ++q) { tse += r3[0][q]; tsx += r3[1][q]; tsy += r3[2][q]; }
        float denom = tse + 4096.f * e0;
        float gx = tsx / denom;
        float gy = tsy / denom;
        size_t ob = (size_t)dir * 32768 + (((size_t)b * 64 + (pos >> 6)) * 64 + (pos & 63)) * 2;
        out[ob]     = gx;
        out[ob + 1] = gy;
    }
}

// ---------------------------------------------------------------------------
__global__ void zero_kernel(float* __restrict__ out)
{
    int i = blockIdx.x * blockDim.x + threadIdx.x;
    int base = (i < 16384) ? 16384 : 49152;
    out[base + (i & 16383)] = 0.f;
}

// ---------------------------------------------------------------------------
extern "C" void kernel_launch(void* const* d_in, const int* in_sizes, int n_in,
                              void* d_out, int out_size)
{
    const float* s3 = (const float*)d_in[0];
    const float* t3 = (const float*)d_in[1];
    const float* s4 = (const float*)d_in[2];
    const float* t4 = (const float*)d_in[3];
    float* out = (float*)d_out;

    cudaFuncSetAttribute(gemm_mma_kernel<0>, cudaFuncAttributeMaxDynamicSharedMemorySize, SMEM_DYN);
    cudaFuncSetAttribute(gemm_mma_kernel<1>, cudaFuncAttributeMaxDynamicSharedMemorySize, SMEM_DYN);

    norm_kernel<<<dim3(32, 4), 256>>>(s3, t3, s4, t4);
    gemm_mma_kernel<0><<<dim3(32, 32, NB), 256, SMEM_DYN>>>(t3, s3);
    gemm_mma_kernel<1><<<dim3(32, 32, NB), 256, SMEM_DYN>>>(t4, s4);
    softargmax_kernel<<<dim3(HW, NB, 2), 256>>>(out);
    zero_kernel<<<64, 512>>>(out);
}

// round 11
// speedup vs baseline: 2.5088x; 1.0398x over previous
#include <cuda_runtime.h>
#include <cuda_fp16.h>
#include <stdint.h>
#include <math.h>

#define HW 4096
#define NB 2

__device__ float g_M [(size_t)NB * HW * HW];   // M[b][j][i]
__device__ float g_MT[(size_t)NB * HW * HW];   // M[b][i][j]
__device__ float g_inv[4][NB * HW];            // 0:src3 1:tgt3 2:src4 3:tgt4

// fp16 hi/lo limb planes, K-major: [limb][b][pos][C]
#define N3 ((size_t)NB * HW * 1024)
#define N4 ((size_t)NB * HW * 2048)
__device__ __align__(256) __half g_h3s[2][N3];
__device__ __align__(256) __half g_h3t[2][N3];
__device__ __align__(256) __half g_h4s[2][N4];
__device__ __align__(256) __half g_h4t[2][N4];

// ---------------------------------------------------------------------------
// PTX helpers (base sm_80 features only -> legal at compute_103)
// ---------------------------------------------------------------------------
__device__ __forceinline__ uint32_t su32(const void* p) {
    uint32_t a;
    asm("{ .reg .u64 t; cvta.to.shared.u64 t, %1; cvt.u32.u64 %0, t; }" : "=r"(a) : "l"(p));
    return a;
}
__device__ __forceinline__ void ldmx4(uint32_t* r, uint32_t a) {
    asm volatile("ldmatrix.sync.aligned.m8n8.x4.shared.b16 {%0,%1,%2,%3}, [%4];"
                 : "=r"(r[0]), "=r"(r[1]), "=r"(r[2]), "=r"(r[3]) : "r"(a));
}
__device__ __forceinline__ void ldmx2(uint32_t* r, uint32_t a) {
    asm volatile("ldmatrix.sync.aligned.m8n8.x2.shared.b16 {%0,%1}, [%2];"
                 : "=r"(r[0]), "=r"(r[1]) : "r"(a));
}
__device__ __forceinline__ void mma16816(float* d, const uint32_t* a, const uint32_t* b) {
    asm volatile(
        "mma.sync.aligned.m16n8k16.row.col.f32.f16.f16.f32 "
        "{%0,%1,%2,%3}, {%4,%5,%6,%7}, {%8,%9}, {%0,%1,%2,%3};"
        : "+f"(d[0]), "+f"(d[1]), "+f"(d[2]), "+f"(d[3])
        : "r"(a[0]), "r"(a[1]), "r"(a[2]), "r"(a[3]), "r"(b[0]), "r"(b[1]));
}
__device__ __forceinline__ void cpasync16(uint32_t dst, const void* src) {
    asm volatile("cp.async.cg.shared.global [%0], [%1], 16;" :: "r"(dst), "l"(src));
}
__device__ __forceinline__ void cp_commit() { asm volatile("cp.async.commit_group;"); }
__device__ __forceinline__ void cp_wait1()  { asm volatile("cp.async.wait_group 1;"); }
__device__ __forceinline__ void cp_wait0()  { asm volatile("cp.async.wait_group 0;"); }

// ---------------------------------------------------------------------------
// Kernel 1: per-position inverse channel norms.
// ---------------------------------------------------------------------------
__global__ void norm_kernel(const float* __restrict__ s3, const float* __restrict__ t3,
                            const float* __restrict__ s4, const float* __restrict__ t4)
{
    int gid   = blockIdx.x * 256 + threadIdx.x;
    int which = blockIdx.y;
    const float* x; int C;
    if      (which == 0) { x = s3; C = 1024; }
    else if (which == 1) { x = t3; C = 1024; }
    else if (which == 2) { x = s4; C = 2048; }
    else                 { x = t4; C = 2048; }

    int b = gid >> 12, pos = gid & (HW - 1);
    const float* p = x + (size_t)b * C * HW + pos;
    float ss0 = 0.f, ss1 = 0.f, ss2 = 0.f, ss3 = 0.f;
    for (int c = 0; c < C; c += 4) {
        float a0 = p[(size_t)(c + 0) * HW];
        float a1 = p[(size_t)(c + 1) * HW];
        float a2 = p[(size_t)(c + 2) * HW];
        float a3 = p[(size_t)(c + 3) * HW];
        ss0 = fmaf(a0, a0, ss0); ss1 = fmaf(a1, a1, ss1);
        ss2 = fmaf(a2, a2, ss2); ss3 = fmaf(a3, a3, ss3);
    }
    g_inv[which][gid] = rsqrtf((ss0 + ss1) + (ss2 + ss3) + 1e-6f);
}

// ---------------------------------------------------------------------------
// Kernel 1b: fp16 hi/lo split + transpose prepass.
// [b][C][HW] fp32 -> hi/lo __half planes [b][HW][C].
// h = rn_f16(v), l = rn_f16(v - h): exact 2-limb split, residual ~2^-22 |v|.
// grid (HW/64, C/32, NB) x 256
// ---------------------------------------------------------------------------
__global__ void __launch_bounds__(256)
split_kernel(const float* __restrict__ in, int which, int C)
{
    __shared__ float tile[32][65];
    __half* hi; __half* lo;
    if      (which == 0) { hi = g_h3s[0]; lo = g_h3s[1]; }
    else if (which == 1) { hi = g_h3t[0]; lo = g_h3t[1]; }
    else if (which == 2) { hi = g_h4s[0]; lo = g_h4s[1]; }
    else                 { hi = g_h4t[0]; lo = g_h4t[1]; }

    const int p0 = blockIdx.x * 64, c0 = blockIdx.y * 32, b = blockIdx.z;
    const float* src = in + (size_t)b * C * HW;
    const int tid = threadIdx.x;

#pragma unroll
    for (int l = 0; l < 8; ++l) {
        int idx = tid + l * 256;
        int c = idx >> 6, p = idx & 63;
        tile[c][p] = src[(size_t)(c0 + c) * HW + p0 + p];
    }
    __syncthreads();

    const int p = tid >> 2, cg = tid & 3;     // 64 pos x 4 groups of 8 c
    union { __half h[8]; uint4 u; } H, L;
#pragma unroll
    for (int e = 0; e < 8; ++e) {
        float v = tile[cg * 8 + e][p];
        __half h = __float2half_rn(v);
        H.h[e] = h;
        L.h[e] = __float2half_rn(v - __half2float(h));
    }
    size_t o = ((size_t)b * HW + p0 + p) * C + c0 + cg * 8;
    *reinterpret_cast<uint4*>(hi + o) = H.u;
    *reinterpret_cast<uint4*>(lo + o) = L.u;
}

// ---------------------------------------------------------------------------
// Kernel 2: fp16-limb mma.sync GEMM fed by cp.async from prequantized planes.
// CTA tile 128(j) x 128(i), K-chunk 32, 8 warps of 64x32, double-buffered.
// Buffer (32KB): Ah 8K | Al 8K | Bh 8K | Bl 8K.  Row = 64B (32 k halves),
// 16B chunks swizzled: c ^= (x>>1)&3.
//   MODE 0: g_M = relu(D * invT3[j] * invS3[i])
//   MODE 1: m = g_M * relu(D * invT4[j] * invS4[i]); g_M = m; g_MT^T = m
// ---------------------------------------------------------------------------
#define SMEM_DYN 65536

template<int MODE>
__global__ void __launch_bounds__(256)
gemm_hmma_kernel()
{
    constexpr int C   = MODE ? 2048 : 1024;
    constexpr int NCH = C / 32;
    constexpr int TI  = MODE ? 3 : 1;
    constexpr int SI  = MODE ? 2 : 0;

    extern __shared__ __align__(16) char sm[];

    const int tid  = threadIdx.x;
    const int lane = tid & 31;
    const int wid  = tid >> 5;
    const int wj   = wid >> 2;           // 0..1 (64 rows each)
    const int wi   = wid & 3;            // 0..3 (32 cols each)
    const int b  = blockIdx.z;
    const int i0 = blockIdx.x * 128;
    const int j0 = blockIdx.y * 128;

    const __half* Ahp = MODE ? g_h4t[0] : g_h3t[0];
    const __half* Alp = MODE ? g_h4t[1] : g_h3t[1];
    const __half* Bhp = MODE ? g_h4s[0] : g_h3s[0];
    const __half* Blp = MODE ? g_h4s[1] : g_h3s[1];

    const uint32_t sb0 = su32(sm);

    // cp.async mapping: thread -> (x = tid>>1, c-pair = (tid&1)*2), 8 xfers/chunk
    const int xa = tid >> 1, cp0 = (tid & 1) * 2;
    const uint32_t swz = (uint32_t)((xa >> 1) & 3);
    const size_t rowA = ((size_t)b * HW + j0 + xa) * C;
    const size_t rowB = ((size_t)b * HW + i0 + xa) * C;

    // ldmatrix address components (row = x*64B, 16B chunk swizzle (x>>1)&3)
    uint32_t aoff[4], aSw[4];
#pragma unroll
    for (int mi = 0; mi < 4; ++mi) {
        int r = wj * 64 + mi * 16 + (lane & 15);
        aoff[mi] = (uint32_t)(r * 64);
        aSw[mi]  = (uint32_t)((r >> 1) & 3);
    }
    const uint32_t hi16 = (uint32_t)((lane >> 4) & 1);
    const int ln = lane & 15;
    uint32_t boff[4], bSw[4];
#pragma unroll
    for (int ni = 0; ni < 4; ++ni) {
        int r = wi * 32 + ni * 8 + (ln & 7);
        boff[ni] = (uint32_t)(r * 64);
        bSw[ni]  = (uint32_t)((r >> 1) & 3);
    }
    const uint32_t bHalf = (uint32_t)((ln >> 3) & 1);

    float acc[4][4][4];
#pragma unroll
    for (int mi = 0; mi < 4; ++mi)
#pragma unroll
        for (int ni = 0; ni < 4; ++ni)
#pragma unroll
            for (int e = 0; e < 4; ++e) acc[mi][ni][e] = 0.f;

    auto issue = [&](int t, int buf) {
        const uint32_t db = sb0 + (uint32_t)buf * 32768u;
        const size_t k = (size_t)t * 32;
#pragma unroll
        for (int c = cp0; c < cp0 + 2; ++c) {
            uint32_t doff = (uint32_t)(xa * 64) + ((((uint32_t)c ^ swz) & 3u) << 4);
            cpasync16(db + doff,           Ahp + rowA + k + c * 8);
            cpasync16(db + 8192u + doff,   Alp + rowA + k + c * 8);
            cpasync16(db + 16384u + doff,  Bhp + rowB + k + c * 8);
            cpasync16(db + 24576u + doff,  Blp + rowB + k + c * 8);
        }
        cp_commit();
    };

    issue(0, 0);
    issue(1, 1);

    for (int t = 0; t < NCH; ++t) {
        if (t + 1 < NCH) cp_wait1(); else cp_wait0();
        __syncthreads();

        const uint32_t sb = sb0 + (uint32_t)((t & 1) * 32768);
#pragma unroll
        for (int ks = 0; ks < 2; ++ks) {
            uint32_t ah[4][4], al[4][4];
#pragma unroll
            for (int mi = 0; mi < 4; ++mi) {
                uint32_t adr = sb + aoff[mi] + ((((uint32_t)(2 * ks) + hi16) ^ aSw[mi]) << 4);
                ldmx4(ah[mi], adr);
                ldmx4(al[mi], adr + 8192u);
            }
#pragma unroll
            for (int ni = 0; ni < 4; ++ni) {
                uint32_t badr = sb + 16384u + boff[ni] +
                                ((((uint32_t)(2 * ks) + bHalf) ^ bSw[ni]) << 4);
                uint32_t bh[2], bl[2];
                ldmx2(bh, badr);
                ldmx2(bl, badr + 8192u);
#pragma unroll
                for (int mi = 0; mi < 4; ++mi) {
                    mma16816(acc[mi][ni], ah[mi], bh);
                    mma16816(acc[mi][ni], ah[mi], bl);
                    mma16816(acc[mi][ni], al[mi], bh);
                }
            }
        }
        __syncthreads();
        if (t + 2 < NCH) issue(t + 2, t & 1);
    }

    // ---- epilogue: scale, relu, store (proven in R9) ----
    const float* invT = g_inv[TI] + (size_t)b * HW;
    const float* invS = g_inv[SI] + (size_t)b * HW;
    const int gid = lane >> 2, tig = lane & 3;
    const int jb = j0 + wj * 64 + gid;
    const int ib = i0 + wi * 32 + tig * 2;

    float tS[4][2];
#pragma unroll
    for (int mi = 0; mi < 4; ++mi) {
        tS[mi][0] = __ldg(invT + jb + mi * 16);
        tS[mi][1] = __ldg(invT + jb + mi * 16 + 8);
    }
    float2 sS[4];
#pragma unroll
    for (int ni = 0; ni < 4; ++ni)
        sS[ni] = *reinterpret_cast<const float2*>(invS + ib + ni * 8);

#pragma unroll
    for (int mi = 0; mi < 4; ++mi) {
        const int j = jb + mi * 16;
        const size_t row0 = ((size_t)b * HW + j) * HW;
        const size_t row8 = row0 + (size_t)8 * HW;
#pragma unroll
        for (int ni = 0; ni < 4; ++ni) {
            const int i = ib + ni * 8;
            float c0 = fmaxf(acc[mi][ni][0] * tS[mi][0] * sS[ni].x, 0.f);
            float c1 = fmaxf(acc[mi][ni][1] * tS[mi][0] * sS[ni].y, 0.f);
            float c2 = fmaxf(acc[mi][ni][2] * tS[mi][1] * sS[ni].x, 0.f);
            float c3 = fmaxf(acc[mi][ni][3] * tS[mi][1] * sS[ni].y, 0.f);
            if (MODE == 0) {
                *reinterpret_cast<float2*>(&g_M[row0 + i]) = make_float2(c0, c1);
                *reinterpret_cast<float2*>(&g_M[row8 + i]) = make_float2(c2, c3);
            } else {
                float2 o0 = *reinterpret_cast<const float2*>(&g_M[row0 + i]);
                float2 o8 = *reinterpret_cast<const float2*>(&g_M[row8 + i]);
                float m0 = o0.x * c0, m1 = o0.y * c1;
                float m2 = o8.x * c2, m3 = o8.y * c3;
                *reinterpret_cast<float2*>(&g_M[row0 + i]) = make_float2(m0, m1);
                *reinterpret_cast<float2*>(&g_M[row8 + i]) = make_float2(m2, m3);
                const size_t tc0 = ((size_t)b * HW + i) * HW;
                g_MT[tc0 + j]          = m0;
                g_MT[tc0 + HW + j]     = m1;
                g_MT[tc0 + j + 8]      = m2;
                g_MT[tc0 + HW + j + 8] = m3;
            }
        }
    }
}

// ---------------------------------------------------------------------------
// Kernel 3: soft-argmax per column (unchanged).
// ---------------------------------------------------------------------------
__global__ void __launch_bounds__(256)
softargmax_kernel(float* __restrict__ out)
{
    __shared__ float gtab[64];
    __shared__ float redf[8];
    __shared__ int   redi[8];
    __shared__ float bc[2];
    __shared__ float r3[3][8];

    const int pos = blockIdx.x;
    const int b   = blockIdx.y;
    const int dir = blockIdx.z;
    const int tid = threadIdx.x;
    const int lane = tid & 31, wid = tid >> 5;

    const float* row = (dir == 0 ? g_MT : g_M) + ((size_t)b * HW + pos) * HW;

    if (tid < 64) gtab[tid] = expf(-(float)(tid * tid) * (1.0f / 50.0f));

    float xr[16];
    float ss = 0.f;
#pragma unroll
    for (int s = 0; s < 16; ++s) {
        float x = row[tid + s * 256];
        xr[s] = x;
        ss = fmaf(x, x, ss);
    }
    for (int o = 16; o; o >>= 1) ss += __shfl_down_sync(0xffffffffu, ss, o);
    if (lane == 0) redf[wid] = ss;
    __syncthreads();
    if (wid == 0) {
        float v = (lane < 8) ? redf[lane] : 0.f;
        for (int o = 4; o; o >>= 1) v += __shfl_down_sync(0xffffffffu, v, o);
        if (lane == 0) bc[0] = rsqrtf(v + 1e-6f);
    }
    __syncthreads();
    const float invn = bc[0];

    float bvv = -1.f; int bj = HW;
#pragma unroll
    for (int s = 0; s < 16; ++s) {
        float x = xr[s];
        int j = tid + s * 256;
        if (x > bvv) { bvv = x; bj = j; }
    }
    for (int o = 16; o; o >>= 1) {
        float ov = __shfl_down_sync(0xffffffffu, bvv, o);
        int   oj = __shfl_down_sync(0xffffffffu, bj,  o);
        if (ov > bvv || (ov == bvv && oj < bj)) { bvv = ov; bj = oj; }
    }
    __syncthreads();
    if (lane == 0) { redf[wid] = bvv; redi[wid] = bj; }
    __syncthreads();
    if (tid == 0) {
        float bestv = redf[0]; int bestj = redi[0];
        for (int q = 1; q < 8; ++q)
            if (redf[q] > bestv || (redf[q] == bestv && redi[q] < bestj)) {
                bestv = redf[q]; bestj = redi[q];
            }
        redi[0] = bestj;
    }
    __syncthreads();
    const int amax = redi[0];
    const int ax = amax & 63, ay = amax >> 6;

    float cm = -1.f;
#pragma unroll
    for (int s = 0; s < 16; ++s) {
        int j = tid + s * 256;
        int dx = (j & 63) - ax; dx = dx < 0 ? -dx : dx;
        int dy = (j >> 6) - ay; dy = dy < 0 ? -dy : dy;
        float g = gtab[dx] * gtab[dy];
        float c = (g < 1e-6f) ? -1.f : g * xr[s] * invn;
        xr[s] = c;
        cm = fmaxf(cm, c);
    }
    for (int o = 16; o; o >>= 1) cm = fmaxf(cm, __shfl_down_sync(0xffffffffu, cm, o));
    __syncthreads();
    if (lane == 0) redf[wid] = cm;
    __syncthreads();
    if (wid == 0) {
        float v = (lane < 8) ? redf[lane] : -1.f;
        for (int o = 4; o; o >>= 1) v = fmaxf(v, __shfl_down_sync(0xffffffffu, v, o));
        if (lane == 0) bc[1] = v;
    }
    __syncthreads();
    const float m  = bc[1];
    const float e0 = __expf(-50.f * m);

    float se = 0.f, sx = 0.f, sy = 0.f;
#pragma unroll
    for (int s = 0; s < 16; ++s) {
        float c = xr[s];
        if (c >= 0.f) {
            int j = tid + s * 256;
            float e = __expf(50.f * (c - m)) - e0;
            float xn = fmaf((float)(j & 63), 2.f / 63.f, -1.f);
            float yn = fmaf((float)(j >> 6), 2.f / 63.f, -1.f);
            se += e;
            sx = fmaf(e, xn, sx);
            sy = fmaf(e, yn, sy);
        }
    }
    for (int o = 16; o; o >>= 1) {
        se += __shfl_down_sync(0xffffffffu, se, o);
        sx += __shfl_down_sync(0xffffffffu, sx, o);
        sy += __shfl_down_sync(0xffffffffu, sy, o);
    }
    if (lane == 0) { r3[0][wid] = se; r3[1][wid] = sx; r3[2][wid] = sy; }
    __syncthreads();
    if (tid == 0) {
        float tse = 0.f, tsx = 0.f, tsy = 0.f;
        for (int q = 0; q < 8; ++q) { tse += r3[0][q]; tsx += r3[1][q]; tsy += r3[2][q]; }
        float denom = tse + 4096.f * e0;
        float gx = tsx / denom;
        float gy = tsy / denom;
        size_t ob = (size_t)dir * 32768 + (((size_t)b * 64 + (pos >> 6)) * 64 + (pos & 63)) * 2;
        out[ob]     = gx;
        out[ob + 1] = gy;
    }
}

// ---------------------------------------------------------------------------
__global__ void zero_kernel(float* __restrict__ out)
{
    int i = blockIdx.x * blockDim.x + threadIdx.x;
    int base = (i < 16384) ? 16384 : 49152;
    out[base + (i & 16383)] = 0.f;
}

// ---------------------------------------------------------------------------
extern "C" void kernel_launch(void* const* d_in, const int* in_sizes, int n_in,
                              void* d_out, int out_size)
{
    const float* s3 = (const float*)d_in[0];
    const float* t3 = (const float*)d_in[1];
    const float* s4 = (const float*)d_in[2];
    const float* t4 = (const float*)d_in[3];
    float* out = (float*)d_out;

    cudaFuncSetAttribute(gemm_hmma_kernel<0>, cudaFuncAttributeMaxDynamicSharedMemorySize, SMEM_DYN);
    cudaFuncSetAttribute(gemm_hmma_kernel<1>, cudaFuncAttributeMaxDynamicSharedMemorySize, SMEM_DYN);

    norm_kernel<<<dim3(32, 4), 256>>>(s3, t3, s4, t4);
    split_kernel<<<dim3(64, 32, NB), 256>>>(s3, 0, 1024);
    split_kernel<<<dim3(64, 32, NB), 256>>>(t3, 1, 1024);
    split_kernel<<<dim3(64, 64, NB), 256>>>(s4, 2, 2048);
    split_kernel<<<dim3(64, 64, NB), 256>>>(t4, 3, 2048);
    gemm_hmma_kernel<0><<<dim3(32, 32, NB), 256, SMEM_DYN>>>();
    gemm_hmma_kernel<1><<<dim3(32, 32, NB), 256, SMEM_DYN>>>();
    softargmax_kernel<<<dim3(HW, NB, 2), 256>>>(out);
    zero_kernel<<<64, 512>>>(out);
}

// round 12
// speedup vs baseline: 2.5700x; 1.0244x over previous
#include <cuda_runtime.h>
#include <cuda_fp16.h>
#include <stdint.h>
#include <math.h>

#define HW 4096
#define NB 2

__device__ float g_M [(size_t)NB * HW * HW];   // M[b][j][i]
__device__ float g_MT[(size_t)NB * HW * HW];   // M[b][i][j]
__device__ float g_inv[4][NB * HW];            // 0:src3 1:tgt3 2:src4 3:tgt4

// fp16 hi/lo limb planes, K-major: [limb][b][pos][C]
#define N3 ((size_t)NB * HW * 1024)
#define N4 ((size_t)NB * HW * 2048)
__device__ __align__(256) __half g_h3s[2][N3];
__device__ __align__(256) __half g_h3t[2][N3];
__device__ __align__(256) __half g_h4s[2][N4];
__device__ __align__(256) __half g_h4t[2][N4];

// ---------------------------------------------------------------------------
// PTX helpers (base sm_80 features only -> legal at compute_103)
// ---------------------------------------------------------------------------
__device__ __forceinline__ uint32_t su32(const void* p) {
    uint32_t a;
    asm("{ .reg .u64 t; cvta.to.shared.u64 t, %1; cvt.u32.u64 %0, t; }" : "=r"(a) : "l"(p));
    return a;
}
__device__ __forceinline__ void ldmx4(uint32_t* r, uint32_t a) {
    asm volatile("ldmatrix.sync.aligned.m8n8.x4.shared.b16 {%0,%1,%2,%3}, [%4];"
                 : "=r"(r[0]), "=r"(r[1]), "=r"(r[2]), "=r"(r[3]) : "r"(a));
}
__device__ __forceinline__ void mma16816(float* d, const uint32_t* a, const uint32_t* b) {
    asm volatile(
        "mma.sync.aligned.m16n8k16.row.col.f32.f16.f16.f32 "
        "{%0,%1,%2,%3}, {%4,%5,%6,%7}, {%8,%9}, {%0,%1,%2,%3};"
        : "+f"(d[0]), "+f"(d[1]), "+f"(d[2]), "+f"(d[3])
        : "r"(a[0]), "r"(a[1]), "r"(a[2]), "r"(a[3]), "r"(b[0]), "r"(b[1]));
}
__device__ __forceinline__ void cpasync16(uint32_t dst, const void* src) {
    asm volatile("cp.async.cg.shared.global [%0], [%1], 16;" :: "r"(dst), "l"(src));
}
__device__ __forceinline__ void cp_commit() { asm volatile("cp.async.commit_group;"); }
__device__ __forceinline__ void cp_wait1()  { asm volatile("cp.async.wait_group 1;"); }
__device__ __forceinline__ void cp_wait0()  { asm volatile("cp.async.wait_group 0;"); }

// ---------------------------------------------------------------------------
// Kernel 1: per-position inverse channel norms.
// ---------------------------------------------------------------------------
__global__ void norm_kernel(const float* __restrict__ s3, const float* __restrict__ t3,
                            const float* __restrict__ s4, const float* __restrict__ t4)
{
    int gid   = blockIdx.x * 256 + threadIdx.x;
    int which = blockIdx.y;
    const float* x; int C;
    if      (which == 0) { x = s3; C = 1024; }
    else if (which == 1) { x = t3; C = 1024; }
    else if (which == 2) { x = s4; C = 2048; }
    else                 { x = t4; C = 2048; }

    int b = gid >> 12, pos = gid & (HW - 1);
    const float* p = x + (size_t)b * C * HW + pos;
    float ss0 = 0.f, ss1 = 0.f, ss2 = 0.f, ss3 = 0.f;
    for (int c = 0; c < C; c += 4) {
        float a0 = p[(size_t)(c + 0) * HW];
        float a1 = p[(size_t)(c + 1) * HW];
        float a2 = p[(size_t)(c + 2) * HW];
        float a3 = p[(size_t)(c + 3) * HW];
        ss0 = fmaf(a0, a0, ss0); ss1 = fmaf(a1, a1, ss1);
        ss2 = fmaf(a2, a2, ss2); ss3 = fmaf(a3, a3, ss3);
    }
    g_inv[which][gid] = rsqrtf((ss0 + ss1) + (ss2 + ss3) + 1e-6f);
}

// ---------------------------------------------------------------------------
// Kernel 1b: fp16 hi/lo split + transpose prepass, 64c x 64p tiles.
// Writes are 128B-contiguous bursts (8 threads x 16B).
// grid (HW/64, C/64, NB) x 256
// ---------------------------------------------------------------------------
__global__ void __launch_bounds__(256)
split_kernel(const float* __restrict__ in, int which, int C)
{
    __shared__ float tile[64][65];
    __half* hi; __half* lo;
    if      (which == 0) { hi = g_h3s[0]; lo = g_h3s[1]; }
    else if (which == 1) { hi = g_h3t[0]; lo = g_h3t[1]; }
    else if (which == 2) { hi = g_h4s[0]; lo = g_h4s[1]; }
    else                 { hi = g_h4t[0]; lo = g_h4t[1]; }

    const int p0 = blockIdx.x * 64, c0 = blockIdx.y * 64, b = blockIdx.z;
    const float* src = in + (size_t)b * C * HW;
    const int tid = threadIdx.x;

#pragma unroll
    for (int l = 0; l < 16; ++l) {
        int idx = tid + l * 256;              // 4096
        int c = idx >> 6, p = idx & 63;
        tile[c][p] = src[(size_t)(c0 + c) * HW + p0 + p];
    }
    __syncthreads();

    const int cg = tid & 7;                   // 8 c-groups of 8
#pragma unroll
    for (int pass = 0; pass < 2; ++pass) {
        const int p = (tid >> 3) + pass * 32;
        union { __half h[8]; uint4 u; } H, L;
#pragma unroll
        for (int e = 0; e < 8; ++e) {
            float v = tile[cg * 8 + e][p];
            __half h = __float2half_rn(v);
            H.h[e] = h;
            L.h[e] = __float2half_rn(v - __half2float(h));
        }
        size_t o = ((size_t)b * HW + p0 + p) * C + c0 + cg * 8;
        *reinterpret_cast<uint4*>(hi + o) = H.u;
        *reinterpret_cast<uint4*>(lo + o) = L.u;
    }
}

// ---------------------------------------------------------------------------
// Kernel 2: fp16-limb mma.sync GEMM, 3-stage cp.async pipeline, single
// __syncthreads per chunk.  CTA tile 128(j) x 128(i), K-chunk 32,
// 8 warps of 64x32.  Buffer (32KB): Ah 8K | Al 8K | Bh 8K | Bl 8K.
// Row = 64B, 16B chunks swizzled: c ^= (x>>1)&3.
//   MODE 0: g_M = relu(D * invT3[j] * invS3[i])
//   MODE 1: m = g_M * relu(D * invT4[j] * invS4[i]); g_M = m; g_MT^T = m
// ---------------------------------------------------------------------------
#define SMEM_DYN (3 * 32768)

template<int MODE>
__global__ void __launch_bounds__(256, 2)
gemm_hmma_kernel()
{
    constexpr int C   = MODE ? 2048 : 1024;
    constexpr int NCH = C / 32;
    constexpr int TI  = MODE ? 3 : 1;
    constexpr int SI  = MODE ? 2 : 0;

    extern __shared__ __align__(16) char sm[];

    const int tid  = threadIdx.x;
    const int lane = tid & 31;
    const int wid  = tid >> 5;
    const int wj   = wid >> 2;           // 0..1 (64 rows each)
    const int wi   = wid & 3;            // 0..3 (32 cols each)
    const int b  = blockIdx.z;
    const int i0 = blockIdx.x * 128;
    const int j0 = blockIdx.y * 128;

    const __half* Ahp = MODE ? g_h4t[0] : g_h3t[0];
    const __half* Alp = MODE ? g_h4t[1] : g_h3t[1];
    const __half* Bhp = MODE ? g_h4s[0] : g_h3s[0];
    const __half* Blp = MODE ? g_h4s[1] : g_h3s[1];

    const uint32_t sb0 = su32(sm);

    // cp.async mapping: thread -> (x = tid>>1, c-pair = (tid&1)*2)
    const int xa = tid >> 1, cp0 = (tid & 1) * 2;
    const uint32_t swz = (uint32_t)((xa >> 1) & 3);
    const size_t rowA = ((size_t)b * HW + j0 + xa) * C;
    const size_t rowB = ((size_t)b * HW + i0 + xa) * C;

    // A ldmatrix components (proven in R9/R11)
    uint32_t aoff[4], aSw[4];
#pragma unroll
    for (int mi = 0; mi < 4; ++mi) {
        int r = wj * 64 + mi * 16 + (lane & 15);
        aoff[mi] = (uint32_t)(r * 64);
        aSw[mi]  = (uint32_t)((r >> 1) & 3);
    }
    const uint32_t hi16 = (uint32_t)((lane >> 4) & 1);

    // B ldmatrix x4 components: lanes 0-15 -> ni = 2np, lanes 16-31 -> 2np+1;
    // (lane>>3)&1 selects the k-half within the ks step.
    uint32_t boff4[2], bSw4[2];
#pragma unroll
    for (int np = 0; np < 2; ++np) {
        int r = wi * 32 + (2 * np + ((lane >> 4) & 1)) * 8 + (lane & 7);
        boff4[np] = (uint32_t)(r * 64);
        bSw4[np]  = (uint32_t)((r >> 1) & 3);
    }
    const uint32_t khB = (uint32_t)((lane >> 3) & 1);

    float acc[4][4][4];
#pragma unroll
    for (int mi = 0; mi < 4; ++mi)
#pragma unroll
        for (int ni = 0; ni < 4; ++ni)
#pragma unroll
            for (int e = 0; e < 4; ++e) acc[mi][ni][e] = 0.f;

    auto issue = [&](int t, int buf) {
        const uint32_t db = sb0 + (uint32_t)buf * 32768u;
        const size_t k = (size_t)t * 32;
#pragma unroll
        for (int c = cp0; c < cp0 + 2; ++c) {
            uint32_t doff = (uint32_t)(xa * 64) + ((((uint32_t)c ^ swz) & 3u) << 4);
            cpasync16(db + doff,           Ahp + rowA + k + c * 8);
            cpasync16(db + 8192u + doff,   Alp + rowA + k + c * 8);
            cpasync16(db + 16384u + doff,  Bhp + rowB + k + c * 8);
            cpasync16(db + 24576u + doff,  Blp + rowB + k + c * 8);
        }
        cp_commit();
    };

    issue(0, 0);
    issue(1, 1);

    int bcur = 0;
    for (int t = 0; t < NCH; ++t) {
        if (t + 1 < NCH) cp_wait1(); else cp_wait0();
        __syncthreads();
        if (t + 2 < NCH) {
            int bn = bcur + 2; if (bn >= 3) bn -= 3;
            issue(t + 2, bn);
        }

        const uint32_t sb = sb0 + (uint32_t)bcur * 32768u;
#pragma unroll
        for (int ks = 0; ks < 2; ++ks) {
            uint32_t ah[4][4], al[4][4];
#pragma unroll
            for (int mi = 0; mi < 4; ++mi) {
                uint32_t adr = sb + aoff[mi] + ((((uint32_t)(2 * ks) + hi16) ^ aSw[mi]) << 4);
                ldmx4(ah[mi], adr);
                ldmx4(al[mi], adr + 8192u);
            }
            uint32_t bqh[2][4], bql[2][4];
#pragma unroll
            for (int np = 0; np < 2; ++np) {
                uint32_t badr = sb + 16384u + boff4[np] +
                                ((((uint32_t)(2 * ks) + khB) ^ bSw4[np]) << 4);
                ldmx4(bqh[np], badr);
                ldmx4(bql[np], badr + 8192u);
            }
#pragma unroll
            for (int np = 0; np < 2; ++np)
#pragma unroll
                for (int sub = 0; sub < 2; ++sub) {
                    const int ni = np * 2 + sub;
                    const uint32_t* bh = &bqh[np][2 * sub];
                    const uint32_t* bl = &bql[np][2 * sub];
#pragma unroll
                    for (int mi = 0; mi < 4; ++mi) {
                        mma16816(acc[mi][ni], ah[mi], bh);
                        mma16816(acc[mi][ni], ah[mi], bl);
                        mma16816(acc[mi][ni], al[mi], bh);
                    }
                }
        }
        if (++bcur == 3) bcur = 0;
    }

    // ---- epilogue: scale, relu, store (proven in R9) ----
    const float* invT = g_inv[TI] + (size_t)b * HW;
    const float* invS = g_inv[SI] + (size_t)b * HW;
    const int gid = lane >> 2, tig = lane & 3;
    const int jb = j0 + wj * 64 + gid;
    const int ib = i0 + wi * 32 + tig * 2;

    float tS[4][2];
#pragma unroll
    for (int mi = 0; mi < 4; ++mi) {
        tS[mi][0] = __ldg(invT + jb + mi * 16);
        tS[mi][1] = __ldg(invT + jb + mi * 16 + 8);
    }
    float2 sS[4];
#pragma unroll
    for (int ni = 0; ni < 4; ++ni)
        sS[ni] = *reinterpret_cast<const float2*>(invS + ib + ni * 8);

#pragma unroll
    for (int mi = 0; mi < 4; ++mi) {
        const int j = jb + mi * 16;
        const size_t row0 = ((size_t)b * HW + j) * HW;
        const size_t row8 = row0 + (size_t)8 * HW;
#pragma unroll
        for (int ni = 0; ni < 4; ++ni) {
            const int i = ib + ni * 8;
            float c0 = fmaxf(acc[mi][ni][0] * tS[mi][0] * sS[ni].x, 0.f);
            float c1 = fmaxf(acc[mi][ni][1] * tS[mi][0] * sS[ni].y, 0.f);
            float c2 = fmaxf(acc[mi][ni][2] * tS[mi][1] * sS[ni].x, 0.f);
            float c3 = fmaxf(acc[mi][ni][3] * tS[mi][1] * sS[ni].y, 0.f);
            if (MODE == 0) {
                *reinterpret_cast<float2*>(&g_M[row0 + i]) = make_float2(c0, c1);
                *reinterpret_cast<float2*>(&g_M[row8 + i]) = make_float2(c2, c3);
            } else {
                float2 o0 = *reinterpret_cast<const float2*>(&g_M[row0 + i]);
                float2 o8 = *reinterpret_cast<const float2*>(&g_M[row8 + i]);
                float m0 = o0.x * c0, m1 = o0.y * c1;
                float m2 = o8.x * c2, m3 = o8.y * c3;
                *reinterpret_cast<float2*>(&g_M[row0 + i]) = make_float2(m0, m1);
                *reinterpret_cast<float2*>(&g_M[row8 + i]) = make_float2(m2, m3);
                const size_t tc0 = ((size_t)b * HW + i) * HW;
                g_MT[tc0 + j]          = m0;
                g_MT[tc0 + HW + j]     = m1;
                g_MT[tc0 + j + 8]      = m2;
                g_MT[tc0 + HW + j + 8] = m3;
            }
        }
    }
}

// ---------------------------------------------------------------------------
// Kernel 3: soft-argmax per column (unchanged).
// ---------------------------------------------------------------------------
__global__ void __launch_bounds__(256)
softargmax_kernel(float* __restrict__ out)
{
    __shared__ float gtab[64];
    __shared__ float redf[8];
    __shared__ int   redi[8];
    __shared__ float bc[2];
    __shared__ float r3[3][8];

    const int pos = blockIdx.x;
    const int b   = blockIdx.y;
    const int dir = blockIdx.z;
    const int tid = threadIdx.x;
    const int lane = tid & 31, wid = tid >> 5;

    const float* row = (dir == 0 ? g_MT : g_M) + ((size_t)b * HW + pos) * HW;

    if (tid < 64) gtab[tid] = expf(-(float)(tid * tid) * (1.0f / 50.0f));

    float xr[16];
    float ss = 0.f;
#pragma unroll
    for (int s = 0; s < 16; ++s) {
        float x = row[tid + s * 256];
        xr[s] = x;
        ss = fmaf(x, x, ss);
    }
    for (int o = 16; o; o >>= 1) ss += __shfl_down_sync(0xffffffffu, ss, o);
    if (lane == 0) redf[wid] = ss;
    __syncthreads();
    if (wid == 0) {
        float v = (lane < 8) ? redf[lane] : 0.f;
        for (int o = 4; o; o >>= 1) v += __shfl_down_sync(0xffffffffu, v, o);
        if (lane == 0) bc[0] = rsqrtf(v + 1e-6f);
    }
    __syncthreads();
    const float invn = bc[0];

    float bvv = -1.f; int bj = HW;
#pragma unroll
    for (int s = 0; s < 16; ++s) {
        float x = xr[s];
        int j = tid + s * 256;
        if (x > bvv) { bvv = x; bj = j; }
    }
    for (int o = 16; o; o >>= 1) {
        float ov = __shfl_down_sync(0xffffffffu, bvv, o);
        int   oj = __shfl_down_sync(0xffffffffu, bj,  o);
        if (ov > bvv || (ov == bvv && oj < bj)) { bvv = ov; bj = oj; }
    }
    __syncthreads();
    if (lane == 0) { redf[wid] = bvv; redi[wid] = bj; }
    __syncthreads();
    if (tid == 0) {
        float bestv = redf[0]; int bestj = redi[0];
        for (int q = 1; q < 8; ++q)
            if (redf[q] > bestv || (redf[q] == bestv && redi[q] < bestj)) {
                bestv = redf[q]; bestj = redi[q];
            }
        redi[0] = bestj;
    }
    __syncthreads();
    const int amax = redi[0];
    const int ax = amax & 63, ay = amax >> 6;

    float cm = -1.f;
#pragma unroll
    for (int s = 0; s < 16; ++s) {
        int j = tid + s * 256;
        int dx = (j & 63) - ax; dx = dx < 0 ? -dx : dx;
        int dy = (j >> 6) - ay; dy = dy < 0 ? -dy : dy;
        float g = gtab[dx] * gtab[dy];
        float c = (g < 1e-6f) ? -1.f : g * xr[s] * invn;
        xr[s] = c;
        cm = fmaxf(cm, c);
    }
    for (int o = 16; o; o >>= 1) cm = fmaxf(cm, __shfl_down_sync(0xffffffffu, cm, o));
    __syncthreads();
    if (lane == 0) redf[wid] = cm;
    __syncthreads();
    if (wid == 0) {
        float v = (lane < 8) ? redf[lane] : -1.f;
        for (int o = 4; o; o >>= 1) v = fmaxf(v, __shfl_down_sync(0xffffffffu, v, o));
        if (lane == 0) bc[1] = v;
    }
    __syncthreads();
    const float m  = bc[1];
    const float e0 = __expf(-50.f * m);

    float se = 0.f, sx = 0.f, sy = 0.f;
#pragma unroll
    for (int s = 0; s < 16; ++s) {
        float c = xr[s];
        if (c >= 0.f) {
            int j = tid + s * 256;
            float e = __expf(50.f * (c - m)) - e0;
            float xn = fmaf((float)(j & 63), 2.f / 63.f, -1.f);
            float yn = fmaf((float)(j >> 6), 2.f / 63.f, -1.f);
            se += e;
            sx = fmaf(e, xn, sx);
            sy = fmaf(e, yn, sy);
        }
    }
    for (int o = 16; o; o >>= 1) {
        se += __shfl_down_sync(0xffffffffu, se, o);
        sx += __shfl_down_sync(0xffffffffu, sx, o);
        sy += __shfl_down_sync(0xffffffffu, sy, o);
    }
    if (lane == 0) { r3[0][wid] = se; r3[1][wid] = sx; r3[2][wid] = sy; }
    __syncthreads();
    if (tid == 0) {
        float tse = 0.f, tsx = 0.f, tsy = 0.f;
        for (int q = 0; q < 8; ++q) { tse += r3[0][q]; tsx += r3[1][q]; tsy += r3[2][q]; }
        float denom = tse + 4096.f * e0;
        float gx = tsx / denom;
        float gy = tsy / denom;
        size_t ob = (size_t)dir * 32768 + (((size_t)b * 64 + (pos >> 6)) * 64 + (pos & 63)) * 2;
        out[ob]     = gx;
        out[ob + 1] = gy;
    }
}

// ---------------------------------------------------------------------------
__global__ void zero_kernel(float* __restrict__ out)
{
    int i = blockIdx.x * blockDim.x + threadIdx.x;
    int base = (i < 16384) ? 16384 : 49152;
    out[base + (i & 16383)] = 0.f;
}

// ---------------------------------------------------------------------------
extern "C" void kernel_launch(void* const* d_in, const int* in_sizes, int n_in,
                              void* d_out, int out_size)
{
    const float* s3 = (const float*)d_in[0];
    const float* t3 = (const float*)d_in[1];
    const float* s4 = (const float*)d_in[2];
    const float* t4 = (const float*)d_in[3];
    float* out = (float*)d_out;

    cudaFuncSetAttribute(gemm_hmma_kernel<0>, cudaFuncAttributeMaxDynamicSharedMemorySize, SMEM_DYN);
    cudaFuncSetAttribute(gemm_hmma_kernel<1>, cudaFuncAttributeMaxDynamicSharedMemorySize, SMEM_DYN);

    norm_kernel<<<dim3(32, 4), 256>>>(s3, t3, s4, t4);
    split_kernel<<<dim3(64, 16, NB), 256>>>(s3, 0, 1024);
    split_kernel<<<dim3(64, 16, NB), 256>>>(t3, 1, 1024);
    split_kernel<<<dim3(64, 32, NB), 256>>>(s4, 2, 2048);
    split_kernel<<<dim3(64, 32, NB), 256>>>(t4, 3, 2048);
    gemm_hmma_kernel<0><<<dim3(32, 32, NB), 256, SMEM_DYN>>>();
    gemm_hmma_kernel<1><<<dim3(32, 32, NB), 256, SMEM_DYN>>>();
    softargmax_kernel<<<dim3(HW, NB, 2), 256>>>(out);
    zero_kernel<<<64, 512>>>(out);
}